// round 4
// baseline (speedup 1.0000x reference)
#include <cuda_runtime.h>

#define NGRAPH 4096
#define EPS 1e-6f

// ---------------- device scratch (no allocations allowed) ----------------
// NOTE: __align__(16) is load-bearing: these are accessed via float4.
__device__ __align__(16) float g_att[262144 * 8];          // unnormalized exp attention [N,8]
__device__ __align__(16) float g_outflat[NGRAPH * 1024];   // aggregated [B, H*D]
__device__ int g_is64;                                     // batch dtype flag

__device__ __forceinline__ float leaky(float x){ return x > 0.f ? x : 0.01f * x; }

// batch may arrive as int32 or int64. Detect with int32 loads only:
// little-endian int64 values in [0,4096) have odd 32-bit words == 0, while
// int32 sorted data in the buffer middle is ~2048 (nonzero) at every position.
__global__ void detect_kernel(const int* __restrict__ batch, int n){
    int base = n / 2;          // middle under int32 view; safe under both
    int ok64 = 1;
    for (int i = 0; i < 256; i++){
        int lo = batch[base + 2*i];
        int hi = batch[base + 2*i + 1];
        if (hi != 0 || lo < 0 || lo >= NGRAPH){ ok64 = 0; break; }
    }
    g_is64 = ok64;
}

// int32-only accessor: for int64 little-endian values < 2^31, the even word
// holds the value.
__device__ __forceinline__ int bat(const int* b, int i, int is64){
    return is64 ? b[2*i] : b[i];
}

__device__ __forceinline__ int lbound(const int* b, int n, int val, int is64){
    int lo = 0, hi = n;
    while (lo < hi){
        int mid = (lo + hi) >> 1;
        if (bat(b, mid, is64) < val) lo = mid + 1; else hi = mid;
    }
    return lo;
}

// ---------------- Pass A: fused GEMM1 + leaky + LN + GEMM2 + exp ----------------
// block = 128 rows, 256 threads.
#define ATT_SMEM_FLOATS (16384 + 8192 + 512 + 64*3 + 8 + 256)

__global__ __launch_bounds__(256) void att_kernel(
    const float* __restrict__ feat,
    const float* __restrict__ W1, const float* __restrict__ b1,
    const float* __restrict__ g1, const float* __restrict__ be1,
    const float* __restrict__ W2, const float* __restrict__ b2)
{
    extern __shared__ float sm[];
    float* sF  = sm;                 // 16384
    float* sW1 = sF  + 16384;        // 8192
    float* sW2 = sW1 + 8192;         // 512
    float* sB1 = sW2 + 512;          // 64
    float* sG1 = sB1 + 64;           // 64
    float* sBe1= sG1 + 64;           // 64
    float* sB2 = sBe1+ 64;           // 8
    float* sMu = sB2 + 8;            // 128
    float* sIs = sMu + 128;          // 128
    float* sH  = sF;                 // alias, row stride 65 (8320 floats < 16384)

    int t = threadIdx.x;
    int row0 = blockIdx.x * 128;

    {   // feat tile 128x128 (4096 float4)
        const float4* gsrc = (const float4*)(feat + (size_t)row0 * 128);
        float4* dst = (float4*)sF;
        #pragma unroll
        for (int e = 0; e < 16; e++) dst[t + 256*e] = gsrc[t + 256*e];
    }
    {   // W1 128x64 (2048 float4)
        const float4* gsrc = (const float4*)W1;
        float4* dst = (float4*)sW1;
        #pragma unroll
        for (int e = 0; e < 8; e++) dst[t + 256*e] = gsrc[t + 256*e];
    }
    if (t < 128) ((float4*)sW2)[t] = ((const float4*)W2)[t];
    if (t < 64){ sB1[t] = b1[t]; sG1[t] = g1[t]; sBe1[t] = be1[t]; }
    if (t < 8)  sB2[t] = b2[t];
    __syncthreads();

    // GEMM1: each thread -> 8 rows x 4 cols
    int tx = t & 15, ty = t >> 4;
    int c0 = tx * 4, r0 = ty * 8;

    float acc[8][4];
    #pragma unroll
    for (int i = 0; i < 8; i++){ acc[i][0]=acc[i][1]=acc[i][2]=acc[i][3]=0.f; }

    const float4* sW1f4 = (const float4*)sW1;   // [k][16]
    for (int k0 = 0; k0 < 128; k0 += 4){
        float4 w0 = sW1f4[(k0+0)*16 + tx];
        float4 w1 = sW1f4[(k0+1)*16 + tx];
        float4 w2 = sW1f4[(k0+2)*16 + tx];
        float4 w3 = sW1f4[(k0+3)*16 + tx];
        #pragma unroll
        for (int i = 0; i < 8; i++){
            float4 a = *(const float4*)&sF[(r0+i)*128 + k0];
            acc[i][0] += a.x*w0.x + a.y*w1.x + a.z*w2.x + a.w*w3.x;
            acc[i][1] += a.x*w0.y + a.y*w1.y + a.z*w2.y + a.w*w3.y;
            acc[i][2] += a.x*w0.z + a.y*w1.z + a.z*w2.z + a.w*w3.z;
            acc[i][3] += a.x*w0.w + a.y*w1.w + a.z*w2.w + a.w*w3.w;
        }
    }
    __syncthreads();   // all sF reads done before aliasing as sH

    #pragma unroll
    for (int i = 0; i < 8; i++)
        #pragma unroll
        for (int q = 0; q < 4; q++)
            sH[(r0+i)*65 + c0 + q] = leaky(acc[i][q] + sB1[c0+q]);
    __syncthreads();

    if (t < 128){   // LN stats per row (stride-65 kills bank conflicts)
        float sum = 0.f, ss = 0.f;
        #pragma unroll 8
        for (int j = 0; j < 64; j++){ float v = sH[t*65 + j]; sum += v; ss += v*v; }
        float mu = sum * (1.f/64.f);
        float var = ss * (1.f/64.f) - mu*mu;
        sMu[t] = mu; sIs[t] = rsqrtf(var + EPS);
    }
    __syncthreads();

    {   // GEMM2 (64->8) + exp, 2 threads per row x 4 outputs
        int row = t >> 1, half = t & 1, kb = half * 4;
        float mu = sMu[row], is = sIs[row];
        float a0=0.f, a1=0.f, a2=0.f, a3=0.f;
        #pragma unroll 4
        for (int j = 0; j < 64; j++){
            float hn = (sH[row*65 + j] - mu) * is * sG1[j] + sBe1[j];
            a0 += hn * sW2[j*8 + kb + 0];
            a1 += hn * sW2[j*8 + kb + 1];
            a2 += hn * sW2[j*8 + kb + 2];
            a3 += hn * sW2[j*8 + kb + 3];
        }
        int grow = row0 + row;
        float4 o;
        o.x = __expf(a0 + sB2[kb+0]);
        o.y = __expf(a1 + sB2[kb+1]);
        o.z = __expf(a2 + sB2[kb+2]);
        o.w = __expf(a3 + sB2[kb+3]);
        *(float4*)&g_att[grow*8 + kb] = o;
    }
}

// ---------------- Pass B: per-graph segment softmax + weighted aggregation ----------------
__global__ __launch_bounds__(256) void aggregate_kernel(
    const float* __restrict__ feat, const int* __restrict__ batchp, int nrows)
{
    int g = blockIdx.x;
    __shared__ int s_lo, s_hi;
    __shared__ float sInv[8];
    // __align__(16) load-bearing: accessed via float4 (static shared arrays
    // otherwise get only 4-byte alignment -> misaligned-address trap).
    __shared__ __align__(16) float sF[8][128];
    __shared__ __align__(16) float sAtt[8][8];

    int is64 = g_is64;
    int t = threadIdx.x;
    if (t == 0) s_lo = lbound(batchp, nrows, g, is64);
    if (t == 32) s_hi = lbound(batchp, nrows, g + 1, is64);
    __syncthreads();
    int lo = s_lo, hi = s_hi;
    int h = t >> 5, lane = t & 31;

    {   // softmax denominator per head (warp h)
        float part = 0.f;
        for (int i = lo + lane; i < hi; i += 32) part += g_att[i*8 + h];
        #pragma unroll
        for (int o = 16; o > 0; o >>= 1) part += __shfl_xor_sync(0xffffffffu, part, o);
        if (lane == 0) sInv[h] = (hi > lo) ? 1.f / part : 0.f;
    }
    __syncthreads();

    float4 acc = make_float4(0.f, 0.f, 0.f, 0.f);
    for (int base = lo; base < hi; base += 8){
        int cnt = min(8, hi - base);
        __syncthreads();
        {
            int r = t >> 5, c4 = t & 31;
            if (r < cnt)
                *(float4*)&sF[r][c4*4] = *(const float4*)&feat[(size_t)(base + r) * 128 + c4*4];
            if (t < 64){
                int r2 = t >> 3, k = t & 7;
                if (r2 < cnt) sAtt[r2][k] = g_att[(base + r2)*8 + k] * sInv[k];
            }
        }
        __syncthreads();
        for (int r = 0; r < cnt; r++){
            float a = sAtt[r][h];
            float4 f = *(const float4*)&sF[r][lane*4];
            acc.x += a*f.x; acc.y += a*f.y; acc.z += a*f.z; acc.w += a*f.w;
        }
    }
    *(float4*)&g_outflat[g*1024 + h*128 + lane*4] = acc;
}

// ---------------- Pass C: [B,1024]@[1024,128]+leaky+LN, then [B,128]@[128,128]+leaky+LN ----------------
#define FIN_SMEM_FLOATS (2048 + 16384 + 2064 + 2064 + 128*6 + 32)

__global__ __launch_bounds__(256) void final_kernel(
    const float* __restrict__ W3, const float* __restrict__ b3,
    const float* __restrict__ g3, const float* __restrict__ be3,
    const float* __restrict__ W4, const float* __restrict__ b4,
    const float* __restrict__ g4, const float* __restrict__ be4,
    float* __restrict__ out)
{
    extern __shared__ float sm[];
    float* sA  = sm;                 // 16x128
    float* sB  = sA  + 2048;         // 128x128 (W3 tile, later W4)
    float* sO1 = sB  + 16384;        // 16x129 padded
    float* sO2 = sO1 + 2064;         // 16x129 padded
    float* sB3 = sO2 + 2064;
    float* sG3 = sB3 + 128;
    float* sBe3= sG3 + 128;
    float* sB4 = sBe3+ 128;
    float* sG4 = sB4 + 128;
    float* sBe4= sG4 + 128;
    float* sMu = sBe4+ 128;          // 16
    float* sIs = sMu + 16;

    int t = threadIdx.x;
    int g0 = blockIdx.x * 16;
    int tx = t & 31, ty = t >> 5;
    int c0 = tx * 4, r0 = ty * 2;

    if (t < 128){
        sB3[t]=b3[t]; sG3[t]=g3[t]; sBe3[t]=be3[t];
        sB4[t]=b4[t]; sG4[t]=g4[t]; sBe4[t]=be4[t];
    }

    // GEMM3: 16x128 output, K=1024 in 8 tiles
    float acc[2][4] = {};
    for (int kt = 0; kt < 8; kt++){
        __syncthreads();
        #pragma unroll
        for (int e = 0; e < 2; e++){
            int idx4 = t + 256*e;
            int r = idx4 >> 5, c4 = idx4 & 31;
            ((float4*)sA)[idx4] = *(const float4*)&g_outflat[(g0 + r)*1024 + kt*128 + c4*4];
        }
        const float4* w3f4 = (const float4*)(W3 + kt*128*128);
        #pragma unroll
        for (int e = 0; e < 16; e++) ((float4*)sB)[t + 256*e] = w3f4[t + 256*e];
        __syncthreads();
        for (int k = 0; k < 128; k++){
            float4 b = ((const float4*)sB)[k*32 + tx];
            #pragma unroll
            for (int i = 0; i < 2; i++){
                float a = sA[(r0+i)*128 + k];
                acc[i][0] += a*b.x; acc[i][1] += a*b.y;
                acc[i][2] += a*b.z; acc[i][3] += a*b.w;
            }
        }
    }
    __syncthreads();

    #pragma unroll
    for (int i = 0; i < 2; i++)
        #pragma unroll
        for (int q = 0; q < 4; q++)
            sO1[(r0+i)*129 + c0 + q] = leaky(acc[i][q] + sB3[c0+q]);
    {   // load W4 into sB (GEMM3 reads of sB complete before the sync above)
        const float4* w4f4 = (const float4*)W4;
        #pragma unroll
        for (int e = 0; e < 16; e++) ((float4*)sB)[t + 256*e] = w4f4[t + 256*e];
    }
    __syncthreads();

    if (t < 16){
        float sum = 0.f, ss = 0.f;
        for (int j = 0; j < 128; j++){ float v = sO1[t*129 + j]; sum += v; ss += v*v; }
        float mu = sum * (1.f/128.f);
        float var = ss * (1.f/128.f) - mu*mu;
        sMu[t] = mu; sIs[t] = rsqrtf(var + EPS);
    }
    __syncthreads();
    #pragma unroll
    for (int e = 0; e < 8; e++){
        int idx = t + 256*e;
        int r = idx >> 7, c = idx & 127;
        sO1[r*129 + c] = (sO1[r*129 + c] - sMu[r]) * sIs[r] * sG3[c] + sBe3[c];
    }
    __syncthreads();

    // GEMM4: 16x128, K=128
    float acc2[2][4] = {};
    for (int k = 0; k < 128; k++){
        float4 b = ((const float4*)sB)[k*32 + tx];
        #pragma unroll
        for (int i = 0; i < 2; i++){
            float a = sO1[(r0+i)*129 + k];
            acc2[i][0] += a*b.x; acc2[i][1] += a*b.y;
            acc2[i][2] += a*b.z; acc2[i][3] += a*b.w;
        }
    }
    #pragma unroll
    for (int i = 0; i < 2; i++)
        #pragma unroll
        for (int q = 0; q < 4; q++)
            sO2[(r0+i)*129 + c0 + q] = leaky(acc2[i][q] + sB4[c0+q]);
    __syncthreads();

    if (t < 16){
        float sum = 0.f, ss = 0.f;
        for (int j = 0; j < 128; j++){ float v = sO2[t*129 + j]; sum += v; ss += v*v; }
        float mu = sum * (1.f/128.f);
        float var = ss * (1.f/128.f) - mu*mu;
        sMu[t] = mu; sIs[t] = rsqrtf(var + EPS);
    }
    __syncthreads();
    #pragma unroll
    for (int e = 0; e < 8; e++){
        int idx = t + 256*e;
        int r = idx >> 7, c = idx & 127;
        out[(g0 + r)*128 + c] = (sO2[r*129 + c] - sMu[r]) * sIs[r] * sG4[c] + sBe4[c];
    }
}

// ---------------- host ----------------
extern "C" void kernel_launch(void* const* d_in, const int* in_sizes, int n_in,
                              void* d_out, int out_size)
{
    const float* feat = (const float*)d_in[0];
    const int*   batch = (const int*)d_in[1];
    const float* W1 = (const float*)d_in[2];
    const float* b1 = (const float*)d_in[3];
    const float* g1 = (const float*)d_in[4];
    const float* be1= (const float*)d_in[5];
    const float* W2 = (const float*)d_in[6];
    const float* b2 = (const float*)d_in[7];
    const float* W3 = (const float*)d_in[8];
    const float* b3 = (const float*)d_in[9];
    const float* g3 = (const float*)d_in[10];
    const float* be3= (const float*)d_in[11];
    const float* W4 = (const float*)d_in[12];
    const float* b4 = (const float*)d_in[13];
    const float* g4 = (const float*)d_in[14];
    const float* be4= (const float*)d_in[15];

    int nrows = in_sizes[0] / 128;

    const int att_smem = ATT_SMEM_FLOATS * (int)sizeof(float);
    const int fin_smem = FIN_SMEM_FLOATS * (int)sizeof(float);
    cudaFuncSetAttribute(att_kernel,   cudaFuncAttributeMaxDynamicSharedMemorySize, att_smem);
    cudaFuncSetAttribute(final_kernel, cudaFuncAttributeMaxDynamicSharedMemorySize, fin_smem);

    detect_kernel<<<1, 1>>>(batch, nrows);
    att_kernel<<<nrows / 128, 256, att_smem>>>(feat, W1, b1, g1, be1, W2, b2);
    aggregate_kernel<<<NGRAPH, 256>>>(feat, batch, nrows);
    final_kernel<<<NGRAPH / 16, 256, fin_smem>>>(W3, b3, g3, be3, W4, b4, g4, be4, (float*)d_out);
}

// round 5
// speedup vs baseline: 1.2846x; 1.2846x over previous
#include <cuda_runtime.h>
#include <cstdint>

#define NGRAPH 4096
#define EPS 1e-6f

// ---------------- device scratch (no allocations allowed) ----------------
__device__ __align__(16) float g_att[262144 * 8];          // exp attention, unnormalized [N,8]
__device__ __align__(16) float g_outflat[NGRAPH * 1024];   // aggregated [B, H*D]
__device__ int g_is64;                                     // batch dtype flag

__device__ __forceinline__ float leaky(float x){ return x > 0.f ? x : 0.01f * x; }

// tf32 round-to-nearest (result in f32 register with low mantissa bits zero)
__device__ __forceinline__ float tf32_rn(float x){
    uint32_t u;
    asm("cvt.rna.tf32.f32 %0, %1;" : "=r"(u) : "f"(x));
    return __uint_as_float(u);
}

// D += A(16x8 tf32) * B(8x8 tf32), fp32 accumulate
__device__ __forceinline__ void mma_tf32(float* c,
    float a0, float a1, float a2, float a3, float b0, float b1){
    asm volatile(
      "mma.sync.aligned.m16n8k8.row.col.f32.tf32.tf32.f32 "
      "{%0,%1,%2,%3}, {%4,%5,%6,%7}, {%8,%9}, {%0,%1,%2,%3};\n"
      : "+f"(c[0]), "+f"(c[1]), "+f"(c[2]), "+f"(c[3])
      : "r"(__float_as_uint(a0)), "r"(__float_as_uint(a1)),
        "r"(__float_as_uint(a2)), "r"(__float_as_uint(a3)),
        "r"(__float_as_uint(b0)), "r"(__float_as_uint(b1)));
}

// batch dtype detection with int32 loads only (little-endian int64 in [0,4096)
// has zero odd words; sorted int32 data in the middle is ~2048 everywhere).
__global__ void detect_kernel(const int* __restrict__ batch, int n){
    int base = n / 2;
    int ok64 = 1;
    for (int i = 0; i < 256; i++){
        int lo = batch[base + 2*i];
        int hi = batch[base + 2*i + 1];
        if (hi != 0 || lo < 0 || lo >= NGRAPH){ ok64 = 0; break; }
    }
    g_is64 = ok64;
}

__device__ __forceinline__ int bat(const int* b, int i, int is64){
    return is64 ? b[2*i] : b[i];
}

__device__ __forceinline__ int lbound(const int* b, int n, int val, int is64){
    int lo = 0, hi = n;
    while (lo < hi){
        int mid = (lo + hi) >> 1;
        if (bat(b, mid, is64) < val) lo = mid + 1; else hi = mid;
    }
    return lo;
}

// ---------------- Pass A: fused GEMM1(tf32 mma) + leaky + LN + GEMM2 + exp ----------------
// 128 rows / block, 256 threads (8 warps, one 16-row M-tile each).
#define AS 132              // sA row stride (floats): banks (4*row + k) distinct
#define WS 68               // sW1 row stride
#define ATT_SMEM_FLOATS (16896 + 8704 + 512 + 64*3 + 8 + 256)

__global__ __launch_bounds__(256) void att_kernel(
    const float* __restrict__ feat,
    const float* __restrict__ W1, const float* __restrict__ b1,
    const float* __restrict__ g1, const float* __restrict__ be1,
    const float* __restrict__ W2, const float* __restrict__ b2)
{
    extern __shared__ float sm[];
    float* sA  = sm;                 // 128 x 132 = 16896 (aliased later as sH stride 65)
    float* sW1 = sA  + 16896;        // 128 x 68  = 8704
    float* sW2 = sW1 + 8704;         // 512
    float* sB1 = sW2 + 512;          // 64
    float* sG1 = sB1 + 64;           // 64
    float* sBe1= sG1 + 64;           // 64
    float* sB2 = sBe1+ 64;           // 8
    float* sMu = sB2 + 8;            // 128
    float* sIs = sMu + 128;          // 128
    float* sH  = sA;                 // alias, stride 65 (8320 <= 16896)

    int t = threadIdx.x;
    int row0 = blockIdx.x * 128;
    int wid = t >> 5, lane = t & 31;
    int g = lane >> 2, t4 = lane & 3;

    {   // feat tile 128x128 -> sA stride 132
        const float4* gsrc = (const float4*)(feat + (size_t)row0 * 128);
        #pragma unroll
        for (int e = 0; e < 16; e++){
            int idx4 = t + 256*e;
            int r = idx4 >> 5, c4 = idx4 & 31;
            *(float4*)&sA[r*AS + 4*c4] = gsrc[idx4];
        }
    }
    {   // W1 128x64 -> sW1 stride 68
        const float4* gsrc = (const float4*)W1;
        #pragma unroll
        for (int e = 0; e < 8; e++){
            int idx4 = t + 256*e;
            int k = idx4 >> 4, c4 = idx4 & 15;
            *(float4*)&sW1[k*WS + 4*c4] = gsrc[idx4];
        }
    }
    if (t < 128) ((float4*)sW2)[t] = ((const float4*)W2)[t];
    if (t < 64){ sB1[t] = b1[t]; sG1[t] = g1[t]; sBe1[t] = be1[t]; }
    if (t < 8)  sB2[t] = b2[t];
    __syncthreads();

    // GEMM1 via tf32 split mma: each warp = 16 rows x 64 cols
    int rbase = wid * 16;
    float acc[8][4];
    #pragma unroll
    for (int j = 0; j < 8; j++){ acc[j][0]=acc[j][1]=acc[j][2]=acc[j][3]=0.f; }

    const float* A0 = sA + (rbase + g) * AS;
    const float* A1 = A0 + 8 * AS;

    #pragma unroll 4
    for (int ks = 0; ks < 16; ks++){
        int k0 = ks * 8;
        float a0 = A0[k0+t4],   a1 = A1[k0+t4];
        float a2 = A0[k0+t4+4], a3 = A1[k0+t4+4];
        float ah0=tf32_rn(a0), ah1=tf32_rn(a1), ah2=tf32_rn(a2), ah3=tf32_rn(a3);
        float al0=tf32_rn(a0-ah0), al1=tf32_rn(a1-ah1), al2=tf32_rn(a2-ah2), al3=tf32_rn(a3-ah3);
        const float* Bk = sW1 + (k0 + t4) * WS + g;
        #pragma unroll
        for (int j = 0; j < 8; j++){
            float b0 = Bk[j*8];
            float b1 = Bk[4*WS + j*8];
            float bh0 = tf32_rn(b0), bh1 = tf32_rn(b1);
            float bl0 = tf32_rn(b0-bh0), bl1 = tf32_rn(b1-bh1);
            mma_tf32(acc[j], ah0,ah1,ah2,ah3, bh0,bh1);
            mma_tf32(acc[j], al0,al1,al2,al3, bh0,bh1);
            mma_tf32(acc[j], ah0,ah1,ah2,ah3, bl0,bl1);
        }
    }
    __syncthreads();   // all sA reads complete before aliasing as sH

    {   // epilogue: bias + leaky -> sH (stride 65)
        int rA = rbase + g, rB = rA + 8;
        #pragma unroll
        for (int j = 0; j < 8; j++){
            int c = j*8 + 2*t4;
            sH[rA*65 + c]     = leaky(acc[j][0] + sB1[c]);
            sH[rA*65 + c + 1] = leaky(acc[j][1] + sB1[c+1]);
            sH[rB*65 + c]     = leaky(acc[j][2] + sB1[c]);
            sH[rB*65 + c + 1] = leaky(acc[j][3] + sB1[c+1]);
        }
    }
    __syncthreads();

    if (t < 128){   // LN stats per row
        float sum = 0.f, ss = 0.f;
        #pragma unroll 8
        for (int j = 0; j < 64; j++){ float v = sH[t*65 + j]; sum += v; ss += v*v; }
        float mu = sum * (1.f/64.f);
        float var = ss * (1.f/64.f) - mu*mu;
        sMu[t] = mu; sIs[t] = rsqrtf(var + EPS);
    }
    __syncthreads();

    {   // GEMM2 (64->8) + exp, 2 threads per row x 4 outputs
        int row = t >> 1, half = t & 1, kb = half * 4;
        float mu = sMu[row], is = sIs[row];
        float a0=0.f, a1=0.f, a2=0.f, a3=0.f;
        #pragma unroll 4
        for (int j = 0; j < 64; j++){
            float hn = (sH[row*65 + j] - mu) * is * sG1[j] + sBe1[j];
            a0 += hn * sW2[j*8 + kb + 0];
            a1 += hn * sW2[j*8 + kb + 1];
            a2 += hn * sW2[j*8 + kb + 2];
            a3 += hn * sW2[j*8 + kb + 3];
        }
        int grow = row0 + row;
        float4 o;
        o.x = __expf(a0 + sB2[kb+0]);
        o.y = __expf(a1 + sB2[kb+1]);
        o.z = __expf(a2 + sB2[kb+2]);
        o.w = __expf(a3 + sB2[kb+3]);
        *(float4*)&g_att[grow*8 + kb] = o;
    }
}

// ---------------- Pass B: single-pass segment softmax + aggregation ----------------
__global__ __launch_bounds__(256) void aggregate_kernel(
    const float* __restrict__ feat, const int* __restrict__ batchp, int nrows)
{
    int gi = blockIdx.x;
    __shared__ int s_lo, s_hi;
    __shared__ __align__(16) float sF[32][128];
    __shared__ __align__(16) float sAtt[32][8];

    int is64 = g_is64;
    int t = threadIdx.x;
    if (t == 0)  s_lo = lbound(batchp, nrows, gi, is64);
    if (t == 32) s_hi = lbound(batchp, nrows, gi + 1, is64);
    __syncthreads();
    int lo = s_lo, hi = s_hi;
    int h = t >> 5, lane = t & 31;

    float4 acc = make_float4(0.f, 0.f, 0.f, 0.f);
    float ssum = 0.f;

    for (int base = lo; base < hi; base += 32){
        int cnt = min(32, hi - base);
        __syncthreads();
        for (int idx4 = t; idx4 < cnt*32; idx4 += 256){
            int r = idx4 >> 5, c4 = idx4 & 31;
            *(float4*)&sF[r][4*c4] = *(const float4*)&feat[(size_t)(base + r) * 128 + 4*c4];
        }
        if (t < cnt*8){
            int r = t >> 3, k = t & 7;
            sAtt[r][k] = g_att[(base + r)*8 + k];
        }
        __syncthreads();
        for (int r = 0; r < cnt; r++){
            float a = sAtt[r][h];
            ssum += a;
            float4 f = *(const float4*)&sF[r][lane*4];
            acc.x += a*f.x; acc.y += a*f.y; acc.z += a*f.z; acc.w += a*f.w;
        }
    }
    float inv = (hi > lo) ? 1.f / ssum : 0.f;
    acc.x *= inv; acc.y *= inv; acc.z *= inv; acc.w *= inv;
    *(float4*)&g_outflat[gi*1024 + h*128 + lane*4] = acc;
}

// ---------------- Pass C: GEMM3(tf32)+leaky+LN, GEMM4(tf32)+leaky+LN ----------------
// 16 graphs / block, 256 blocks, 256 threads. Warp w owns n-tiles {2w, 2w+1}.
#define FS 132
#define FIN_SMEM_FLOATS (2112 + 16896 + 128*6 + 32)

__global__ __launch_bounds__(256) void final_kernel(
    const float* __restrict__ W3, const float* __restrict__ b3,
    const float* __restrict__ g3, const float* __restrict__ be3,
    const float* __restrict__ W4, const float* __restrict__ b4,
    const float* __restrict__ g4, const float* __restrict__ be4,
    float* __restrict__ out)
{
    extern __shared__ float sm[];
    float* sA  = sm;                 // 16 x 132 = 2112 (aliased as sO1)
    float* sW  = sA + 2112;          // 128 x 132 = 16896 (W3 tile -> W4 -> sO2)
    float* sB3 = sW + 16896;
    float* sG3 = sB3 + 128;
    float* sBe3= sG3 + 128;
    float* sB4 = sBe3+ 128;
    float* sG4 = sB4 + 128;
    float* sBe4= sG4 + 128;
    float* sMu = sBe4+ 128;          // 16
    float* sIs = sMu + 16;           // 16

    int t = threadIdx.x;
    int g0 = blockIdx.x * 16;
    int wid = t >> 5, lane = t & 31;
    int g = lane >> 2, t4 = lane & 3;

    if (t < 128){
        sB3[t]=b3[t]; sG3[t]=g3[t]; sBe3[t]=be3[t];
        sB4[t]=b4[t]; sG4[t]=g4[t]; sBe4[t]=be4[t];
    }

    // ---- GEMM3: [16,1024] @ [1024,128], 8 k-tiles of 128 ----
    float acc[2][4];
    acc[0][0]=acc[0][1]=acc[0][2]=acc[0][3]=0.f;
    acc[1][0]=acc[1][1]=acc[1][2]=acc[1][3]=0.f;

    for (int kt = 0; kt < 8; kt++){
        __syncthreads();
        {   // stage A: 16 x 128 (512 float4)
            int idx4 = t + ((t < 256) ? 0 : 0);  // 512 float4, 2 per thread
            #pragma unroll
            for (int e = 0; e < 2; e++){
                int i4 = t + 256*e;
                if (i4 < 512){
                    int r = i4 >> 5, c4 = i4 & 31;
                    *(float4*)&sA[r*FS + 4*c4] =
                        *(const float4*)&g_outflat[(g0 + r)*1024 + kt*128 + 4*c4];
                }
            }
            (void)idx4;
        }
        {   // stage W3 k-tile: 128 x 128 (4096 float4)
            const float* wsrc = W3 + (size_t)kt * 128 * 128;
            #pragma unroll
            for (int e = 0; e < 16; e++){
                int i4 = t + 256*e;
                int r = i4 >> 5, c4 = i4 & 31;
                *(float4*)&sW[r*FS + 4*c4] = *(const float4*)&wsrc[r*128 + 4*c4];
            }
        }
        __syncthreads();

        const float* A0 = sA + g * FS;
        const float* A1 = sA + (g + 8) * FS;
        #pragma unroll 4
        for (int ks = 0; ks < 16; ks++){
            int k0 = ks * 8;
            float a0 = A0[k0+t4],   a1 = A1[k0+t4];
            float a2 = A0[k0+t4+4], a3 = A1[k0+t4+4];
            float ah0=tf32_rn(a0), ah1=tf32_rn(a1), ah2=tf32_rn(a2), ah3=tf32_rn(a3);
            float al0=tf32_rn(a0-ah0), al1=tf32_rn(a1-ah1), al2=tf32_rn(a2-ah2), al3=tf32_rn(a3-ah3);
            const float* Bk = sW + (k0 + t4) * FS + wid*16 + g;
            #pragma unroll
            for (int jj = 0; jj < 2; jj++){
                float b0 = Bk[jj*8];
                float b1 = Bk[4*FS + jj*8];
                float bh0 = tf32_rn(b0), bh1 = tf32_rn(b1);
                float bl0 = tf32_rn(b0-bh0), bl1 = tf32_rn(b1-bh1);
                mma_tf32(acc[jj], ah0,ah1,ah2,ah3, bh0,bh1);
                mma_tf32(acc[jj], al0,al1,al2,al3, bh0,bh1);
                mma_tf32(acc[jj], ah0,ah1,ah2,ah3, bl0,bl1);
            }
        }
    }
    __syncthreads();

    float* sO1 = sA;   // 16 x 132 alias
    {   // epilogue GEMM3 -> sO1; stage W4 -> sW
        #pragma unroll
        for (int jj = 0; jj < 2; jj++){
            int c = wid*16 + jj*8 + 2*t4;
            sO1[g*FS + c]       = leaky(acc[jj][0] + sB3[c]);
            sO1[g*FS + c + 1]   = leaky(acc[jj][1] + sB3[c+1]);
            sO1[(g+8)*FS + c]   = leaky(acc[jj][2] + sB3[c]);
            sO1[(g+8)*FS + c+1] = leaky(acc[jj][3] + sB3[c+1]);
        }
        #pragma unroll
        for (int e = 0; e < 16; e++){
            int i4 = t + 256*e;
            int r = i4 >> 5, c4 = i4 & 31;
            *(float4*)&sW[r*FS + 4*c4] = *(const float4*)&W4[r*128 + 4*c4];
        }
    }
    __syncthreads();

    if (t < 16){   // LN1 stats
        float sum = 0.f, ss = 0.f;
        #pragma unroll 8
        for (int j = 0; j < 128; j++){ float v = sO1[t*FS + j]; sum += v; ss += v*v; }
        float mu = sum * (1.f/128.f);
        float var = ss * (1.f/128.f) - mu*mu;
        sMu[t] = mu; sIs[t] = rsqrtf(var + EPS);
    }
    __syncthreads();
    #pragma unroll
    for (int e = 0; e < 8; e++){
        int idx = t + 256*e;
        int r = idx >> 7, c = idx & 127;
        sO1[r*FS + c] = (sO1[r*FS + c] - sMu[r]) * sIs[r] * sG3[c] + sBe3[c];
    }
    __syncthreads();

    // ---- GEMM4: [16,128] @ [128,128] ----
    float acc2[2][4];
    acc2[0][0]=acc2[0][1]=acc2[0][2]=acc2[0][3]=0.f;
    acc2[1][0]=acc2[1][1]=acc2[1][2]=acc2[1][3]=0.f;
    {
        const float* A0 = sO1 + g * FS;
        const float* A1 = sO1 + (g + 8) * FS;
        #pragma unroll 4
        for (int ks = 0; ks < 16; ks++){
            int k0 = ks * 8;
            float a0 = A0[k0+t4],   a1 = A1[k0+t4];
            float a2 = A0[k0+t4+4], a3 = A1[k0+t4+4];
            float ah0=tf32_rn(a0), ah1=tf32_rn(a1), ah2=tf32_rn(a2), ah3=tf32_rn(a3);
            float al0=tf32_rn(a0-ah0), al1=tf32_rn(a1-ah1), al2=tf32_rn(a2-ah2), al3=tf32_rn(a3-ah3);
            const float* Bk = sW + (k0 + t4) * FS + wid*16 + g;
            #pragma unroll
            for (int jj = 0; jj < 2; jj++){
                float b0 = Bk[jj*8];
                float b1 = Bk[4*FS + jj*8];
                float bh0 = tf32_rn(b0), bh1 = tf32_rn(b1);
                float bl0 = tf32_rn(b0-bh0), bl1 = tf32_rn(b1-bh1);
                mma_tf32(acc2[jj], ah0,ah1,ah2,ah3, bh0,bh1);
                mma_tf32(acc2[jj], al0,al1,al2,al3, bh0,bh1);
                mma_tf32(acc2[jj], ah0,ah1,ah2,ah3, bl0,bl1);
            }
        }
    }
    __syncthreads();   // all sW (W4) reads done

    float* sO2 = sW;   // 16 x 132 alias inside W4 region
    #pragma unroll
    for (int jj = 0; jj < 2; jj++){
        int c = wid*16 + jj*8 + 2*t4;
        sO2[g*FS + c]       = leaky(acc2[jj][0] + sB4[c]);
        sO2[g*FS + c + 1]   = leaky(acc2[jj][1] + sB4[c+1]);
        sO2[(g+8)*FS + c]   = leaky(acc2[jj][2] + sB4[c]);
        sO2[(g+8)*FS + c+1] = leaky(acc2[jj][3] + sB4[c+1]);
    }
    __syncthreads();

    if (t < 16){   // LN2 stats
        float sum = 0.f, ss = 0.f;
        #pragma unroll 8
        for (int j = 0; j < 128; j++){ float v = sO2[t*FS + j]; sum += v; ss += v*v; }
        float mu = sum * (1.f/128.f);
        float var = ss * (1.f/128.f) - mu*mu;
        sMu[t] = mu; sIs[t] = rsqrtf(var + EPS);
    }
    __syncthreads();
    #pragma unroll
    for (int e = 0; e < 8; e++){
        int idx = t + 256*e;
        int r = idx >> 7, c = idx & 127;
        out[(g0 + r)*128 + c] = (sO2[r*FS + c] - sMu[r]) * sIs[r] * sG4[c] + sBe4[c];
    }
}

// ---------------- host ----------------
extern "C" void kernel_launch(void* const* d_in, const int* in_sizes, int n_in,
                              void* d_out, int out_size)
{
    const float* feat = (const float*)d_in[0];
    const int*   batch = (const int*)d_in[1];
    const float* W1 = (const float*)d_in[2];
    const float* b1 = (const float*)d_in[3];
    const float* g1 = (const float*)d_in[4];
    const float* be1= (const float*)d_in[5];
    const float* W2 = (const float*)d_in[6];
    const float* b2 = (const float*)d_in[7];
    const float* W3 = (const float*)d_in[8];
    const float* b3 = (const float*)d_in[9];
    const float* g3 = (const float*)d_in[10];
    const float* be3= (const float*)d_in[11];
    const float* W4 = (const float*)d_in[12];
    const float* b4 = (const float*)d_in[13];
    const float* g4 = (const float*)d_in[14];
    const float* be4= (const float*)d_in[15];

    int nrows = in_sizes[0] / 128;

    const int att_smem = ATT_SMEM_FLOATS * (int)sizeof(float);
    const int fin_smem = FIN_SMEM_FLOATS * (int)sizeof(float);
    cudaFuncSetAttribute(att_kernel,   cudaFuncAttributeMaxDynamicSharedMemorySize, att_smem);
    cudaFuncSetAttribute(final_kernel, cudaFuncAttributeMaxDynamicSharedMemorySize, fin_smem);

    detect_kernel<<<1, 1>>>(batch, nrows);
    att_kernel<<<nrows / 128, 256, att_smem>>>(feat, W1, b1, g1, be1, W2, b2);
    aggregate_kernel<<<NGRAPH, 256>>>(feat, batch, nrows);
    final_kernel<<<NGRAPH / 16, 256, fin_smem>>>(W3, b3, g3, be3, W4, b4, g4, be4, (float*)d_out);
}